// round 14
// baseline (speedup 1.0000x reference)
#include <cuda_runtime.h>
#include <math.h>

// Problem constants (fixed by setup_inputs)
#define XY 10
#define Zdim 5
#define S 500
#define NT 10000
#define Bsz 32
#define Tlen 40
#define Llen 20
#define LOG2E 1.4426950408889634f
#define LN2   0.6931471805599453f

__device__ __forceinline__ float ex2(float x) {
    float r; asm("ex2.approx.ftz.f32 %0, %1;" : "=f"(r) : "f"(x)); return r;
}
__device__ __forceinline__ float lg2(float x) {
    float r; asm("lg2.approx.ftz.f32 %0, %1;" : "=f"(r) : "f"(x)); return r;
}

// ---------------------------------------------------------------------------
// Kernel 1: emission sums (transpose-free), output in log2 domain.
// ---------------------------------------------------------------------------
__global__ void __launch_bounds__(512, 2) em_kernel(
    const float* __restrict__ logE,
    const int* __restrict__ stories,
    float* __restrict__ out)
{
    extern __shared__ float sh[];          // [NT][2] interleaved = 80000 B
    const int s0 = blockIdx.x * 2;

    const float4* r0 = (const float4*)(logE + (long)s0 * NT);
    const float4* r1 = (const float4*)(logE + (long)(s0 + 1) * NT);
    for (int i = threadIdx.x; i < NT / 4; i += blockDim.x) {
        float4 a = __ldg(&r0[i]);
        float4 b = __ldg(&r1[i]);
        int t4 = i * 4;
        sh[(t4 + 0) * 2 + 0] = a.x; sh[(t4 + 0) * 2 + 1] = b.x;
        sh[(t4 + 1) * 2 + 0] = a.y; sh[(t4 + 1) * 2 + 1] = b.y;
        sh[(t4 + 2) * 2 + 0] = a.z; sh[(t4 + 2) * 2 + 1] = b.z;
        sh[(t4 + 3) * 2 + 0] = a.w; sh[(t4 + 3) * 2 + 1] = b.w;
    }
    __syncthreads();

    const float2* sh2 = (const float2*)sh;
    for (int bt = threadIdx.x; bt < Bsz * Tlen; bt += blockDim.x) {
        const int4* tp = (const int4*)(stories + bt * Llen);
        int4 q0 = __ldg(&tp[0]);
        int4 q1 = __ldg(&tp[1]);
        int4 q2 = __ldg(&tp[2]);
        int4 q3 = __ldg(&tp[3]);
        int4 q4 = __ldg(&tp[4]);
        float ax = 0.f, ay = 0.f;
#define GATH(tk) { float2 v = sh2[tk]; ax += v.x; ay += v.y; }
        GATH(q0.x) GATH(q0.y) GATH(q0.z) GATH(q0.w)
        GATH(q1.x) GATH(q1.y) GATH(q1.z) GATH(q1.w)
        GATH(q2.x) GATH(q2.y) GATH(q2.z) GATH(q2.w)
        GATH(q3.x) GATH(q3.y) GATH(q3.z) GATH(q3.w)
        GATH(q4.x) GATH(q4.y) GATH(q4.z) GATH(q4.w)
#undef GATH
        int b = bt / Tlen;
        int t = bt % Tlen;
        float2* op = (float2*)(out + ((long)t * Bsz + b) * S + s0);
        *op = make_float2(ax * LOG2E, ay * LOG2E);   // log2 domain
    }
}

// ---------------------------------------------------------------------------
// Kernel 2: forward recursion; 2 x-adjacent states per thread (256 threads,
// 8 warps). p[s] = m[s]*2^e[s], m in [1,2); own states' (m,e) live in
// registers across steps; shared float4 (m_a,e_a,m_b,e_b) per pair for
// neighbor exchange. Recurrence path is FFMA/IMNMX/bit-ALU only.
// ---------------------------------------------------------------------------
__global__ void __launch_bounds__(256, 1) forward_kernel(
    const float* __restrict__ prior,
    const float* __restrict__ logT,
    float* __restrict__ out)
{
    __shared__ float4 buf[2][256];
    const int p = threadIdx.x;           // pair index: states a=2p, b=2p+1
    const int bb = blockIdx.x;
    const bool act = (p < S / 2);
    const int BS = Bsz * S;
    const int a = 2 * p;

    const int za = a / 100, ra = a % 100, ya = ra / 10, xa = ra % 10; // xa even
    const bool vxm = (xa > 0), vxp = (xa < 8);
    const bool vym = (ya > 0), vyp = (ya < 9);
    const bool vzp = (za < Zdim - 1), vzpp = (za < Zdim - 2);

    const int pxm = vxm ? p - 1  : p;
    const int pxp = vxp ? p + 1  : p;
    const int pym = vym ? p - 5  : p;
    const int pyp = vyp ? p + 5  : p;
    const int pzp = vzp ? p + 50 : p;
    const int pzpp= vzpp? p + 100: p;

    // Linear-domain weights (order: self,+x,-x,+y,-y,+z,+2z)
    float wa[7], wb[7];
    if (act) {
        const float* rowA = logT + (long)a * S;
        const float* rowB = logT + (long)(a + 1) * S;
        wa[0] = ex2(__ldg(&rowA[a]) * LOG2E);
        wa[1] = ex2(__ldg(&rowA[a + 1]) * LOG2E);
        wa[2] = vxm ? ex2(__ldg(&rowA[a - 1]) * LOG2E) : 0.f;
        wa[3] = vyp ? ex2(__ldg(&rowA[a + 10]) * LOG2E) : 0.f;
        wa[4] = vym ? ex2(__ldg(&rowA[a - 10]) * LOG2E) : 0.f;
        wa[5] = vzp ? ex2(__ldg(&rowA[a + 100]) * LOG2E) : 0.f;
        wa[6] = vzpp? ex2(__ldg(&rowA[a + 200]) * LOG2E) : 0.f;
        wb[0] = ex2(__ldg(&rowB[a + 1]) * LOG2E);
        wb[1] = vxp ? ex2(__ldg(&rowB[a + 2]) * LOG2E) : 0.f;
        wb[2] = ex2(__ldg(&rowB[a]) * LOG2E);
        wb[3] = vyp ? ex2(__ldg(&rowB[a + 11]) * LOG2E) : 0.f;
        wb[4] = vym ? ex2(__ldg(&rowB[a - 9]) * LOG2E) : 0.f;
        wb[5] = vzp ? ex2(__ldg(&rowB[a + 101]) * LOG2E) : 0.f;
        wb[6] = vzpp? ex2(__ldg(&rowB[a + 201]) * LOG2E) : 0.f;
    }

    // t = 0 seed
    float m_a = 1.f, m_b = 1.f;
    int   e_a = 0,   e_b = 0;
    if (act) {
        float2 em0 = *(const float2*)(out + bb * S + a);
        float2 pr  = *(const float2*)(prior + a);
        float a2a = em0.x + pr.x * LOG2E;
        float a2b = em0.y + pr.y * LOG2E;
        *(float2*)(out + bb * S + a) = make_float2(a2a * LN2, a2b * LN2);
        e_a = __float2int_rd(a2a); m_a = ex2(a2a - (float)e_a);
        e_b = __float2int_rd(a2b); m_b = ex2(a2b - (float)e_b);
        buf[0][p] = make_float4(m_a, __int_as_float(e_a), m_b, __int_as_float(e_b));
    }

    // Prefetch em (float2 = both states) for t=1, t=2
    const float* ep = out + (Bsz + bb) * S + a;
    float2 emA = act ? *(const float2*)(ep)      : make_float2(0.f, 0.f);
    float2 emB = act ? *(const float2*)(ep + BS) : make_float2(0.f, 0.f);
    ep += 2 * BS;

    // em factors for t=1 (off the serial path)
    int   fi_a = __float2int_rd(emA.x), fi_b = __float2int_rd(emA.y);
    float ex_a = ex2(emA.x - (float)fi_a);
    float ex_b = ex2(emA.y - (float)fi_b);
    __syncthreads();

    float* op = out + (Bsz + bb) * S + a;
    int cur = 0;
#pragma unroll 1
    for (int t = 1; t < Tlen; t++) {
        float2 em_next = emA = emB;   // em for t+1 moves up
        if (act && t + 2 < Tlen) emB = *(const float2*)(ep);
        ep += BS;

        if (act) {
            // Neighbor pair loads
            float4 nym = buf[cur][pym];
            float4 nyp = buf[cur][pyp];
            float4 nzp = buf[cur][pzp];
            float4 nzpp= buf[cur][pzpp];
            float2 nxm = *(const float2*)(&buf[cur][pxm].z);  // state 2*pxm+1
            float2 nxp = *(const float2*)(&buf[cur][pxp].x);  // state 2*pxp

            const float pm_a = m_a, pm_b = m_b;   // pre-update own values
            const int   pe_a = e_a, pe_b = e_b;

#define SCLB(EK, BASE) __int_as_float(max((EK) + (BASE), 0) << 23)
            // ---- state a ----
            {
                int E2 = __float_as_int(nxm.y);
                int E3 = __float_as_int(nyp.y), E4 = __float_as_int(nym.y);
                int E5 = __float_as_int(nzp.y), E6 = __float_as_int(nzpp.y);
                int emax = max(max(max(pe_a, pe_b), max(E2, E3)),
                               max(max(E4, E5), E6));
                int base = 127 - emax;
                float q = wa[0] * pm_a * SCLB(pe_a, base);
                q = fmaf(wa[1] * pm_b,    SCLB(pe_b, base), q);
                q = fmaf(wa[2] * nxm.x,   SCLB(E2, base), q);
                q = fmaf(wa[3] * nyp.x,   SCLB(E3, base), q);
                q = fmaf(wa[4] * nym.x,   SCLB(E4, base), q);
                q = fmaf(wa[5] * nzp.x,   SCLB(E5, base), q);
                q = fmaf(wa[6] * nzpp.x,  SCLB(E6, base), q);
                float tot = q * ex_a;
                int bits = __float_as_int(tot);
                e_a = emax + fi_a + ((bits >> 23) - 127);
                m_a = __int_as_float((bits & 0x007FFFFF) | 0x3F800000);
            }
            // ---- state b ----
            {
                int E1 = __float_as_int(nxp.y);
                int E3 = __float_as_int(nyp.w), E4 = __float_as_int(nym.w);
                int E5 = __float_as_int(nzp.w), E6 = __float_as_int(nzpp.w);
                int emax = max(max(max(pe_b, E1), max(pe_a, E3)),
                               max(max(E4, E5), E6));
                int base = 127 - emax;
                float q = wb[0] * pm_b * SCLB(pe_b, base);
                q = fmaf(wb[1] * nxp.x,   SCLB(E1, base), q);
                q = fmaf(wb[2] * pm_a,    SCLB(pe_a, base), q);
                q = fmaf(wb[3] * nyp.z,   SCLB(E3, base), q);
                q = fmaf(wb[4] * nym.z,   SCLB(E4, base), q);
                q = fmaf(wb[5] * nzp.z,   SCLB(E5, base), q);
                q = fmaf(wb[6] * nzpp.z,  SCLB(E6, base), q);
                float tot = q * ex_b;
                int bits = __float_as_int(tot);
                e_b = emax + fi_b + ((bits >> 23) - 127);
                m_b = __int_as_float((bits & 0x007FFFFF) | 0x3F800000);
            }
#undef SCLB
            // Publish new pair
            buf[cur ^ 1][p] = make_float4(m_a, __int_as_float(e_a),
                                          m_b, __int_as_float(e_b));

            // Output (natural log) — off the serial path
            float oa = ((float)e_a + lg2(m_a)) * LN2;
            float ob = ((float)e_b + lg2(m_b)) * LN2;
            *(float2*)op = make_float2(oa, ob);

            // em factors for next step (off the serial path)
            fi_a = __float2int_rd(em_next.x); fi_b = __float2int_rd(em_next.y);
            ex_a = ex2(em_next.x - (float)fi_a);
            ex_b = ex2(em_next.y - (float)fi_b);
        }
        op += BS;
        __syncthreads();
        cur ^= 1;
    }
}

// ---------------------------------------------------------------------------
extern "C" void kernel_launch(void* const* d_in, const int* in_sizes, int n_in,
                              void* d_out, int out_size) {
    const float* log_priors      = (const float*)d_in[0];
    const float* log_transitions = (const float*)d_in[1];
    const float* log_emissions   = (const float*)d_in[2];
    const int*   stories         = (const int*)d_in[3];
    float* out = (float*)d_out;

    static bool attr_set = false;
    if (!attr_set) {
        cudaFuncSetAttribute(em_kernel,
                             cudaFuncAttributeMaxDynamicSharedMemorySize,
                             NT * 2 * (int)sizeof(float));
        attr_set = true;
    }

    em_kernel<<<S / 2, 512, NT * 2 * sizeof(float)>>>(log_emissions, stories, out);
    forward_kernel<<<Bsz, 256>>>(log_priors, log_transitions, out);
}

// round 17
// speedup vs baseline: 1.0525x; 1.0525x over previous
#include <cuda_runtime.h>
#include <math.h>

// Problem constants (fixed by setup_inputs)
#define XY 10
#define Zdim 5
#define S 500
#define NT 10000
#define Bsz 32
#define Tlen 40
#define Llen 20
#define LOG2E 1.4426950408889634f
#define LN2   0.6931471805599453f

__device__ __forceinline__ float ex2(float x) {
    float r; asm("ex2.approx.ftz.f32 %0, %1;" : "=f"(r) : "f"(x)); return r;
}
__device__ __forceinline__ float lg2(float x) {
    float r; asm("lg2.approx.ftz.f32 %0, %1;" : "=f"(r) : "f"(x)); return r;
}

// ---------------------------------------------------------------------------
// Kernel 1: emission sums (transpose-free), output in log2 domain.
// Each block owns 2 states (2 rows of logE in shared, interleaved [tok][2]).
// ---------------------------------------------------------------------------
__global__ void __launch_bounds__(512, 2) em_kernel(
    const float* __restrict__ logE,
    const int* __restrict__ stories,
    float* __restrict__ out)
{
    extern __shared__ float sh[];          // [NT][2] interleaved = 80000 B
    const int s0 = blockIdx.x * 2;

    const float4* r0 = (const float4*)(logE + (long)s0 * NT);
    const float4* r1 = (const float4*)(logE + (long)(s0 + 1) * NT);
    for (int i = threadIdx.x; i < NT / 4; i += blockDim.x) {
        float4 a = __ldg(&r0[i]);
        float4 b = __ldg(&r1[i]);
        int t4 = i * 4;
        sh[(t4 + 0) * 2 + 0] = a.x; sh[(t4 + 0) * 2 + 1] = b.x;
        sh[(t4 + 1) * 2 + 0] = a.y; sh[(t4 + 1) * 2 + 1] = b.y;
        sh[(t4 + 2) * 2 + 0] = a.z; sh[(t4 + 2) * 2 + 1] = b.z;
        sh[(t4 + 3) * 2 + 0] = a.w; sh[(t4 + 3) * 2 + 1] = b.w;
    }
    __syncthreads();

    const float2* sh2 = (const float2*)sh;
    for (int bt = threadIdx.x; bt < Bsz * Tlen; bt += blockDim.x) {
        const int4* tp = (const int4*)(stories + bt * Llen);
        int4 q0 = __ldg(&tp[0]);
        int4 q1 = __ldg(&tp[1]);
        int4 q2 = __ldg(&tp[2]);
        int4 q3 = __ldg(&tp[3]);
        int4 q4 = __ldg(&tp[4]);
        float ax = 0.f, ay = 0.f;
#define GATH(tk) { float2 v = sh2[tk]; ax += v.x; ay += v.y; }
        GATH(q0.x) GATH(q0.y) GATH(q0.z) GATH(q0.w)
        GATH(q1.x) GATH(q1.y) GATH(q1.z) GATH(q1.w)
        GATH(q2.x) GATH(q2.y) GATH(q2.z) GATH(q2.w)
        GATH(q3.x) GATH(q3.y) GATH(q3.z) GATH(q3.w)
        GATH(q4.x) GATH(q4.y) GATH(q4.z) GATH(q4.w)
#undef GATH
        int b = bt / Tlen;
        int t = bt % Tlen;
        float2* op = (float2*)(out + ((long)t * Bsz + b) * S + s0);
        *op = make_float2(ax * LOG2E, ay * LOG2E);   // log2 domain
    }
}

// ---------------------------------------------------------------------------
// Kernel 2: forward recursion, linear mantissa + per-state int32 exponent
// (R10 structure — measured best). Scale construction uses IMNMX+IMAD
// (2 ALU/neighbor); loop unrolled by 2 via lambda.
// ---------------------------------------------------------------------------
__global__ void __launch_bounds__(512, 1) forward_kernel(
    const float* __restrict__ prior,
    const float* __restrict__ logT,
    float* __restrict__ out)
{
    __shared__ float2 buf[2][512];   // {mantissa, exponent-as-float-bits}
    const int s = threadIdx.x;
    const int b = blockIdx.x;
    const bool act = (s < S);
    const int BS = Bsz * S;

    // Linear-domain sparse transition row (7-neighbor stencil)
    float w[7];
    int   nb[7];
    if (act) {
        int z = s / (XY * XY);
        int r = s % (XY * XY);
        int y = r / XY;
        int x = r % XY;
        const float* row = logT + (long)s * S;
        bool v1 = (x + 1 < XY), v2 = (x - 1 >= 0);
        bool v3 = (y + 1 < XY), v4 = (y - 1 >= 0);
        bool v5 = (z + 1 < Zdim), v6 = (z + 2 < Zdim);
        nb[0] = s;                     w[0] = ex2(__ldg(&row[s]) * LOG2E);
        nb[1] = v1 ? s + 1   : s;      w[1] = v1 ? ex2(__ldg(&row[s + 1]) * LOG2E)   : 0.f;
        nb[2] = v2 ? s - 1   : s;      w[2] = v2 ? ex2(__ldg(&row[s - 1]) * LOG2E)   : 0.f;
        nb[3] = v3 ? s + XY  : s;      w[3] = v3 ? ex2(__ldg(&row[s + XY]) * LOG2E)  : 0.f;
        nb[4] = v4 ? s - XY  : s;      w[4] = v4 ? ex2(__ldg(&row[s - XY]) * LOG2E)  : 0.f;
        nb[5] = v5 ? s + XY*XY   : s;  w[5] = v5 ? ex2(__ldg(&row[s + XY*XY]) * LOG2E)   : 0.f;
        nb[6] = v6 ? s + 2*XY*XY : s;  w[6] = v6 ? ex2(__ldg(&row[s + 2*XY*XY]) * LOG2E) : 0.f;
    }

    // t = 0: alpha2_0 = em2_0 + prior2 (log2 domain). Split into (m, e).
    if (act) {
        float a2 = out[b * S + s] + __ldg(&prior[s]) * LOG2E;
        out[b * S + s] = a2 * LN2;                // natural-log output
        int   e0 = __float2int_rd(a2);
        float m0 = ex2(a2 - (float)e0);           // in [1,2)
        buf[0][s] = make_float2(m0, __int_as_float(e0));
    }

    // Prefetch em for t=1, t=2
    const float* ep = out + (Bsz + b) * S + s;
    float emA = act ? __ldg(&ep[0])  : 0.f;
    float emB = act ? __ldg(&ep[BS]) : 0.f;
    ep += 2 * BS;

    // em factors for t=1 (off the serial path)
    int   fi = __float2int_rd(emA);
    float ef = ex2(emA - (float)fi);
    __syncthreads();

    float* op = out + (Bsz + b) * S + s;

    // One timestep: read pb, write pw. Updates emA/emB/ep/fi/ef/op.
    auto step = [&](const float2* __restrict__ pb, float2* __restrict__ pw,
                    bool more) {
        float em_next = emA = emB;
        if (act & more) emB = __ldg(ep);
        ep += BS;

        if (act) {
            // Load 7 neighbors (m, e)
            float2 n0 = pb[nb[0]], n1 = pb[nb[1]], n2 = pb[nb[2]], n3 = pb[nb[3]];
            float2 n4 = pb[nb[4]], n5 = pb[nb[5]], n6 = pb[nb[6]];
            int e0 = __float_as_int(n0.y), e1 = __float_as_int(n1.y);
            int e2 = __float_as_int(n2.y), e3 = __float_as_int(n3.y);
            int e4 = __float_as_int(n4.y), e5 = __float_as_int(n5.y);
            int e6 = __float_as_int(n6.y);

            int emax = max(max(max(e0, e1), max(e2, e3)),
                           max(max(e4, e5), e6));
            int lo    = emax - 127;               // clamp threshold
            int b23   = (127 - emax) << 23;       // hoisted base in exp position

            // scale_k = 2^(e_k - emax): IMNMX + IMAD per neighbor (exact)
#define SCL(ek) __int_as_float(max(ek, lo) * 8388608 + b23)
            float q = w[0] * n0.x * SCL(e0);
            q = fmaf(w[1] * n1.x, SCL(e1), q);
            q = fmaf(w[2] * n2.x, SCL(e2), q);
            q = fmaf(w[3] * n3.x, SCL(e3), q);
            q = fmaf(w[4] * n4.x, SCL(e4), q);
            q = fmaf(w[5] * n5.x, SCL(e5), q);
            q = fmaf(w[6] * n6.x, SCL(e6), q);
#undef SCL
            // Fold emission, single renorm: tot = q * ef in (2^-140, 2^10)
            float tot = q * ef;
            int bits  = __float_as_int(tot);
            int en    = emax + fi + ((bits >> 23) - 127);
            float mn  = __int_as_float((bits & 0x007FFFFF) | 0x3F800000);

            pw[s] = make_float2(mn, __int_as_float(en));

            // Output alpha (natural log); lg2 only feeds the store
            *op = ((float)en + lg2(mn)) * LN2;

            // em factors for next step (off the serial path)
            fi = __float2int_rd(em_next);
            ef = ex2(em_next - (float)fi);
        }
        op += BS;
        __syncthreads();
    };

    // 39 steps: 19 unrolled pairs + 1 tail
#pragma unroll 1
    for (int t = 1; t < Tlen - 2; t += 2) {
        step(buf[0], buf[1], true);
        step(buf[1], buf[0], t + 3 < Tlen);
    }
    step(buf[0], buf[1], false);   // t = 39

}

// ---------------------------------------------------------------------------
extern "C" void kernel_launch(void* const* d_in, const int* in_sizes, int n_in,
                              void* d_out, int out_size) {
    const float* log_priors      = (const float*)d_in[0];
    const float* log_transitions = (const float*)d_in[1];
    const float* log_emissions   = (const float*)d_in[2];
    const int*   stories         = (const int*)d_in[3];
    float* out = (float*)d_out;

    static bool attr_set = false;
    if (!attr_set) {
        cudaFuncSetAttribute(em_kernel,
                             cudaFuncAttributeMaxDynamicSharedMemorySize,
                             NT * 2 * (int)sizeof(float));
        attr_set = true;
    }

    em_kernel<<<S / 2, 512, NT * 2 * sizeof(float)>>>(log_emissions, stories, out);
    forward_kernel<<<Bsz, 512>>>(log_priors, log_transitions, out);
}